// round 10
// baseline (speedup 1.0000x reference)
#include <cuda_runtime.h>
#include <cstdint>

#define MAX_NODES 50000
__device__ float g_xw[(size_t)MAX_NODES * 128];   // x @ W[64:192] + b (fp32)

// ---------------- helpers ----------------
__device__ __forceinline__ void red_add_v4(float* p, float a, float b, float c, float d) {
    asm volatile("red.global.add.v4.f32 [%0], {%1,%2,%3,%4};"
                 :: "l"(p), "f"(a), "f"(b), "f"(c), "f"(d) : "memory");
}
__device__ __forceinline__ uint32_t tf32r(float f) {
    uint32_t r; asm("cvt.rna.tf32.f32 %0, %1;" : "=r"(r) : "f"(f)); return r;
}
__device__ __forceinline__ uint32_t smem_u32(const void* p) {
    uint32_t a;
    asm("{ .reg .u64 t; cvta.to.shared.u64 t, %1; cvt.u32.u64 %0, t; }" : "=r"(a) : "l"(p));
    return a;
}
__device__ __forceinline__ void cp_async16(uint32_t dst, const void* src) {
    asm volatile("cp.async.cg.shared.global [%0], [%1], 16;" :: "r"(dst), "l"(src));
}
__device__ __forceinline__ void mma_tf32(float& c0, float& c1, float& c2, float& c3,
                                         uint32_t a0, uint32_t a1, uint32_t a2, uint32_t a3,
                                         uint32_t b0, uint32_t b1) {
    asm volatile("mma.sync.aligned.m16n8k8.row.col.f32.tf32.tf32.f32 "
                 "{%0,%1,%2,%3}, {%4,%5,%6,%7}, {%8,%9}, {%0,%1,%2,%3};"
                 : "+f"(c0), "+f"(c1), "+f"(c2), "+f"(c3)
                 : "r"(a0), "r"(a1), "r"(a2), "r"(a3), "r"(b0), "r"(b1));
}
__device__ __forceinline__ float4 ldg_v4(const float* p) {
    float4 v;
    asm volatile("ld.global.nc.v4.f32 {%0,%1,%2,%3}, [%4];"
                 : "=f"(v.x), "=f"(v.y), "=f"(v.z), "=f"(v.w) : "l"(p));
    return v;
}
// logical column for physical fragment column n (each thread's 4 cols contiguous)
__device__ __forceinline__ int colperm(int n) {
    int q = n & 15;
    return (q < 8) ? (n & ~15) + 4 * (q >> 1) + (q & 1)
                   : (n & ~15) + 4 * ((q - 8) >> 1) + 2 + (q & 1);
}

// ---------------------------------------------------------------------------
// Kernel A (fused): blocks [0,NB_ZERO) zero `out`; the rest run the node GEMM
// xW = x @ W[64:192] + b on mma.sync tf32 (K=128 = 2 phases of 64).
// ---------------------------------------------------------------------------
#define NB_ZERO  128
#define NA_OFF   65536
#define NBIAS_OFF 98304
#define NODE_SMEM (NBIAS_OFF + 512)

__global__ __launch_bounds__(256, 2)
void node_fused_kernel(const float* __restrict__ x,
                       const float* __restrict__ W,   // [192][128]
                       const float* __restrict__ b,
                       float* __restrict__ out, int out_n,
                       int N, int ntiles) {
    const int tid = threadIdx.x;

    if (blockIdx.x < NB_ZERO) {               // zero the output buffer
        float4 z = make_float4(0.f, 0.f, 0.f, 0.f);
        int total4 = out_n >> 2;
        for (int i = blockIdx.x * 256 + tid; i < total4; i += NB_ZERO * 256)
            ((float4*)out)[i] = z;
        return;
    }

    extern __shared__ char smem[];
    const uint32_t sb = smem_u32(smem);
    uint2* B_s   = (uint2*)smem;
    float* bias_s = (float*)(smem + NBIAS_OFF);

    const int wid  = tid >> 5, lane = tid & 31;
    const int g    = lane >> 2, t = lane & 3;
    const int wbase = wid * 16;
    const int tile = blockIdx.x - NB_ZERO;
    if (tile >= ntiles) return;
    const int n0 = tile * 128;

    // build B fragments from W rows [64,192): 8192 uint2 entries
#pragma unroll
    for (int it = 0; it < 32; it++) {
        int i = tid + it * 256;
        int c = i & 3, n = (i >> 2) & 127, ks = i >> 9;
        int l = colperm(n);
        int k0 = 64 + ks * 8 + c;
        B_s[i] = make_uint2(tf32r(W[(size_t)k0 * 128 + l]),
                            tf32r(W[(size_t)(k0 + 4) * 128 + l]));
    }
    if (tid < 128) bias_s[tid] = b[tid];

    float acc[16][4];
#pragma unroll
    for (int nt = 0; nt < 16; nt++)
#pragma unroll
        for (int j = 0; j < 4; j++) acc[nt][j] = 0.0f;

    for (int h = 0; h < 2; h++) {
#pragma unroll
        for (int it = 0; it < 8; it++) {
            int i = tid + it * 256;
            int e = i >> 4, q = i & 15;
            int n = n0 + e; if (n > N - 1) n = N - 1;
            uint32_t dst = sb + NA_OFF + e * 256 + ((q ^ (e & 7)) << 4);
            cp_async16(dst, x + (size_t)n * 128 + h * 64 + q * 4);
        }
        asm volatile("cp.async.commit_group;" ::: "memory");
        asm volatile("cp.async.wait_group 0;" ::: "memory");
        __syncthreads();

        const float* Abuf = (const float*)(smem + NA_OFF);
        const float* ar0 = Abuf + (wbase + g) * 64;
        const float* ar1 = Abuf + (wbase + 8 + g) * 64;
#pragma unroll
        for (int ks = 0; ks < 8; ks++) {
            int c0 = (((2 * ks)     ^ g) << 2) + t;
            int c1 = (((2 * ks + 1) ^ g) << 2) + t;
            uint32_t a0 = tf32r(ar0[c0]);
            uint32_t a1 = tf32r(ar1[c0]);
            uint32_t a2 = tf32r(ar0[c1]);
            uint32_t a3 = tf32r(ar1[c1]);
            const uint2* brow = B_s + (h * 8 + ks) * 512 + g * 4 + t;
#pragma unroll
            for (int nt = 0; nt < 16; nt++) {
                uint2 bv = brow[nt * 32];
                mma_tf32(acc[nt][0], acc[nt][1], acc[nt][2], acc[nt][3],
                         a0, a1, a2, a3, bv.x, bv.y);
            }
        }
        if (h == 0) __syncthreads();   // A buffer reused for half 1
    }

    // epilogue: add bias, store fp32 rows of g_xw
#pragma unroll
    for (int rs = 0; rs < 2; rs++) {
        int m = wbase + g + 8 * rs;
        int n = n0 + m;
        if (n >= N) continue;
        float* p = &g_xw[(size_t)n * 128];
#pragma unroll
        for (int q = 0; q < 8; q++) {
            int lc = q * 16 + 4 * t;
            float4 bv = *(const float4*)&bias_s[lc];
            float4 v = make_float4(acc[2 * q    ][rs * 2    ] + bv.x,
                                   acc[2 * q    ][rs * 2 + 1] + bv.y,
                                   acc[2 * q + 1][rs * 2    ] + bv.z,
                                   acc[2 * q + 1][rs * 2 + 1] + bv.w);
            *(float4*)&p[lc] = v;
        }
    }
}

// ---------------------------------------------------------------------------
// Kernel B: warp-autonomous edge pipeline, 384 threads (12 warps), 1 CTA/SM.
// Gather xW[src] prefetched into REGISTERS before the MMA loop (latency hides
// under 128 HMMAs). B fragments packed as uint4 (2 n-tiles per LDS.128).
// smem: B @0 (32KB) | warp w: A bufs 2x4KB @ 32768 + w*8192
// ---------------------------------------------------------------------------
#define AW_OFF  32768
#define EDGE_SMEM (AW_OFF + 12 * 8192)   // 131072

__global__ __launch_bounds__(384, 1)
void edge_mma_kernel(const int* __restrict__ eidx,   // [2][E] int32
                     const float* __restrict__ ea,   // [E][64]
                     const float* __restrict__ W,    // [192][128]
                     float* __restrict__ out,        // [N][128]
                     int E, int N, int nwtiles) {
    extern __shared__ char smem[];
    const uint32_t sb = smem_u32(smem);
    uint2* B2 = (uint2*)smem;
    const uint4* B4 = (const uint4*)smem;

    const int tid  = threadIdx.x;
    const int wid  = tid >> 5, lane = tid & 31;
    const int g    = lane >> 2, t = lane & 3;
    const int tp   = g * 4 + t;

    // build B fragments from W rows [0,64), paired layout:
    // uint4 j = ks*256 + (nt>>1)*32 + tp holds frags for nt=2p (xy), nt=2p+1 (zw)
    for (int i = tid; i < 8192; i += 384) {
        int c = i & 3, n = (i >> 2) & 127, ks = i >> 9;
        int l = colperm(n);
        int k0 = ks * 8 + c;
        uint2 v = make_uint2(tf32r(W[(size_t)k0 * 128 + l]),
                             tf32r(W[(size_t)(k0 + 4) * 128 + l]));
        int nt = n >> 3, gg = n & 7;
        int i2 = ks * 512 + (nt >> 1) * 64 + (gg * 4 + c) * 2 + (nt & 1);
        B2[i2] = v;
    }
    __syncthreads();

    const uint32_t a_base = sb + AW_OFF + wid * 8192;
    const float*   a_ptr0 = (const float*)(smem + AW_OFF + wid * 8192);

    auto issue = [&](int wt2, int p2) {
        size_t ebase = (size_t)wt2 * 16;
#pragma unroll
        for (int it = 0; it < 8; it++) {
            int i = lane + it * 32;          // 256 16B chunks
            int e = i >> 4, q = i & 15;
            size_t se = ebase + e;
            if (se > (size_t)E - 1) se = (size_t)E - 1;
            cp_async16(a_base + p2 * 4096 + e * 256 + ((q ^ (e & 7)) << 4),
                       ea + se * 64 + q * 4);
        }
        asm volatile("cp.async.commit_group;" ::: "memory");
    };

    const int stride = gridDim.x * 12;
    int wt = blockIdx.x * 12 + wid;
    int p = 0;
    int s0 = -1, d0 = -1, s1 = -1, d1 = -1;
    if (wt < nwtiles) {
        issue(wt, 0);
        size_t ebase = (size_t)wt * 16;
        if (ebase + g < (size_t)E) {
            s0 = eidx[ebase + g];
            d0 = eidx[(size_t)E + ebase + g];
        }
        if (ebase + g + 8 < (size_t)E) {
            s1 = eidx[ebase + g + 8];
            d1 = eidx[(size_t)E + ebase + g + 8];
        }
    }

    for (; wt < nwtiles; wt += stride) {
        // (a) gather prefetch into registers (independent of MMA result)
        int ss0 = ((unsigned)s0 < (unsigned)N) ? s0 : 0;
        int ss1 = ((unsigned)s1 < (unsigned)N) ? s1 : 0;
        float4 gv0[8], gv1[8];
        {
            const float* gp0 = g_xw + (size_t)ss0 * 128 + 4 * t;
            const float* gp1 = g_xw + (size_t)ss1 * 128 + 4 * t;
#pragma unroll
            for (int q = 0; q < 8; q++) gv0[q] = ldg_v4(gp0 + q * 16);
#pragma unroll
            for (int q = 0; q < 8; q++) gv1[q] = ldg_v4(gp1 + q * 16);
        }

        // (b) issue next A tile, (c) prefetch next indices
        int next = wt + stride;
        int ns0 = -1, nd0 = -1, ns1 = -1, nd1 = -1;
        __syncwarp();
        if (next < nwtiles) {
            issue(next, p ^ 1);
            size_t nb = (size_t)next * 16;
            if (nb + g < (size_t)E) {
                ns0 = eidx[nb + g];
                nd0 = eidx[(size_t)E + nb + g];
            }
            if (nb + g + 8 < (size_t)E) {
                ns1 = eidx[nb + g + 8];
                nd1 = eidx[(size_t)E + nb + g + 8];
            }
            asm volatile("cp.async.wait_group 1;" ::: "memory");
        } else {
            asm volatile("cp.async.wait_group 0;" ::: "memory");
        }
        __syncwarp();

        // (e) MMA from buffer p
        float acc[16][4];
#pragma unroll
        for (int nt = 0; nt < 16; nt++)
#pragma unroll
            for (int j = 0; j < 4; j++) acc[nt][j] = 0.0f;

        const float* Abuf = a_ptr0 + p * 1024;
        const float* ar0 = Abuf + g * 64;
        const float* ar1 = Abuf + (8 + g) * 64;
#pragma unroll
        for (int ks = 0; ks < 8; ks++) {
            int c0 = (((2 * ks)     ^ g) << 2) + t;
            int c1 = (((2 * ks + 1) ^ g) << 2) + t;
            uint32_t a0 = tf32r(ar0[c0]);
            uint32_t a1 = tf32r(ar1[c0]);
            uint32_t a2 = tf32r(ar0[c1]);
            uint32_t a3 = tf32r(ar1[c1]);
            const uint4* b4 = B4 + ks * 256 + tp;
#pragma unroll
            for (int pp = 0; pp < 8; pp++) {
                uint4 bw = b4[pp * 32];
                mma_tf32(acc[2 * pp    ][0], acc[2 * pp    ][1],
                         acc[2 * pp    ][2], acc[2 * pp    ][3],
                         a0, a1, a2, a3, bw.x, bw.y);
                mma_tf32(acc[2 * pp + 1][0], acc[2 * pp + 1][1],
                         acc[2 * pp + 1][2], acc[2 * pp + 1][3],
                         a0, a1, a2, a3, bw.z, bw.w);
            }
        }

        // (f) epilogue: ReLU(acc + gathered) -> vector atomic scatter
        size_t ebase = (size_t)wt * 16;
#pragma unroll
        for (int rs = 0; rs < 2; rs++) {
            int d = rs ? d1 : d0;
            int m = g + 8 * rs;
            if (ebase + m >= (size_t)E || (unsigned)d >= (unsigned)N) continue;
            float* op = &out[(size_t)d * 128];
            float4* gvp = rs ? gv1 : gv0;
#pragma unroll
            for (int q = 0; q < 8; q++) {
                int lc = q * 16 + 4 * t;
                float4 gvv = gvp[q];
                float v0 = fmaxf(acc[2 * q    ][rs * 2    ] + gvv.x, 0.f);
                float v1 = fmaxf(acc[2 * q    ][rs * 2 + 1] + gvv.y, 0.f);
                float v2 = fmaxf(acc[2 * q + 1][rs * 2    ] + gvv.z, 0.f);
                float v3 = fmaxf(acc[2 * q + 1][rs * 2 + 1] + gvv.w, 0.f);
                red_add_v4(op + lc, v0, v1, v2, v3);
            }
        }
        s0 = ns0; d0 = nd0; s1 = ns1; d1 = nd1;
        p ^= 1;
    }
}

extern "C" void kernel_launch(void* const* d_in, const int* in_sizes, int n_in,
                              void* d_out, int out_size) {
    const float* x    = (const float*)d_in[0];
    const int*   eidx = (const int*)d_in[1];   // int32 [2][E]
    const float* ea   = (const float*)d_in[2];
    const float* W    = (const float*)d_in[3];
    const float* b    = (const float*)d_in[4];
    float* out = (float*)d_out;

    const int N = in_sizes[0] / 128;   // 50000
    const int E = in_sizes[2] / 64;    // 800000
    const int ntilesN = (N + 127) / 128;
    const int nwtiles = (E + 15) / 16;

    cudaFuncSetAttribute(node_fused_kernel,
                         cudaFuncAttributeMaxDynamicSharedMemorySize, NODE_SMEM);
    cudaFuncSetAttribute(edge_mma_kernel,
                         cudaFuncAttributeMaxDynamicSharedMemorySize, EDGE_SMEM);

    node_fused_kernel<<<NB_ZERO + ntilesN, 256, NODE_SMEM>>>(x, W, b, out, out_size, N, ntilesN);

    edge_mma_kernel<<<148, 384, EDGE_SMEM>>>(eidx, ea, W, out, E, N, nwtiles);
}

// round 11
// speedup vs baseline: 1.0363x; 1.0363x over previous
#include <cuda_runtime.h>
#include <cstdint>

#define MAX_NODES 50000
__device__ float g_xw[(size_t)MAX_NODES * 128];   // x @ W[64:192] + b (fp32)

// ---------------- helpers ----------------
__device__ __forceinline__ void red_add_v4(float* p, float a, float b, float c, float d) {
    asm volatile("red.global.add.v4.f32 [%0], {%1,%2,%3,%4};"
                 :: "l"(p), "f"(a), "f"(b), "f"(c), "f"(d) : "memory");
}
__device__ __forceinline__ uint32_t tf32r(float f) {
    uint32_t r; asm("cvt.rna.tf32.f32 %0, %1;" : "=r"(r) : "f"(f)); return r;
}
__device__ __forceinline__ uint32_t smem_u32(const void* p) {
    uint32_t a;
    asm("{ .reg .u64 t; cvta.to.shared.u64 t, %1; cvt.u32.u64 %0, t; }" : "=r"(a) : "l"(p));
    return a;
}
__device__ __forceinline__ void cp_async16(uint32_t dst, const void* src) {
    asm volatile("cp.async.cg.shared.global [%0], [%1], 16;" :: "r"(dst), "l"(src));
}
__device__ __forceinline__ void mma_tf32(float& c0, float& c1, float& c2, float& c3,
                                         uint32_t a0, uint32_t a1, uint32_t a2, uint32_t a3,
                                         uint32_t b0, uint32_t b1) {
    asm volatile("mma.sync.aligned.m16n8k8.row.col.f32.tf32.tf32.f32 "
                 "{%0,%1,%2,%3}, {%4,%5,%6,%7}, {%8,%9}, {%0,%1,%2,%3};"
                 : "+f"(c0), "+f"(c1), "+f"(c2), "+f"(c3)
                 : "r"(a0), "r"(a1), "r"(a2), "r"(a3), "r"(b0), "r"(b1));
}
__device__ __forceinline__ float4 ldg_v4(const float* p) {
    float4 v;
    asm volatile("ld.global.nc.v4.f32 {%0,%1,%2,%3}, [%4];"
                 : "=f"(v.x), "=f"(v.y), "=f"(v.z), "=f"(v.w) : "l"(p));
    return v;
}
// logical column for physical fragment column n (each thread's 4 cols contiguous)
__device__ __forceinline__ int colperm(int n) {
    int q = n & 15;
    return (q < 8) ? (n & ~15) + 4 * (q >> 1) + (q & 1)
                   : (n & ~15) + 4 * ((q - 8) >> 1) + 2 + (q & 1);
}

// ---------------------------------------------------------------------------
// Kernel A (fused): blocks [0,NB_ZERO) zero `out`; the rest run the node GEMM
// xW = x @ W[64:192] + b on mma.sync tf32 (K=128 = 2 phases of 64).
// ---------------------------------------------------------------------------
#define NB_ZERO  128
#define NA_OFF   65536
#define NBIAS_OFF 98304
#define NODE_SMEM (NBIAS_OFF + 512)

__global__ __launch_bounds__(256, 2)
void node_fused_kernel(const float* __restrict__ x,
                       const float* __restrict__ W,   // [192][128]
                       const float* __restrict__ b,
                       float* __restrict__ out, int out_n,
                       int N, int ntiles) {
    const int tid = threadIdx.x;

    if (blockIdx.x < NB_ZERO) {               // zero the output buffer
        float4 z = make_float4(0.f, 0.f, 0.f, 0.f);
        int total4 = out_n >> 2;
        for (int i = blockIdx.x * 256 + tid; i < total4; i += NB_ZERO * 256)
            ((float4*)out)[i] = z;
        return;
    }

    extern __shared__ char smem[];
    const uint32_t sb = smem_u32(smem);
    uint2* B_s   = (uint2*)smem;
    float* bias_s = (float*)(smem + NBIAS_OFF);

    const int wid  = tid >> 5, lane = tid & 31;
    const int g    = lane >> 2, t = lane & 3;
    const int wbase = wid * 16;
    const int tile = blockIdx.x - NB_ZERO;
    if (tile >= ntiles) return;
    const int n0 = tile * 128;

    // build B fragments from W rows [64,192): 8192 uint2 entries
#pragma unroll
    for (int it = 0; it < 32; it++) {
        int i = tid + it * 256;
        int c = i & 3, n = (i >> 2) & 127, ks = i >> 9;
        int l = colperm(n);
        int k0 = 64 + ks * 8 + c;
        B_s[i] = make_uint2(tf32r(W[(size_t)k0 * 128 + l]),
                            tf32r(W[(size_t)(k0 + 4) * 128 + l]));
    }
    if (tid < 128) bias_s[tid] = b[tid];

    float acc[16][4];
#pragma unroll
    for (int nt = 0; nt < 16; nt++)
#pragma unroll
        for (int j = 0; j < 4; j++) acc[nt][j] = 0.0f;

    for (int h = 0; h < 2; h++) {
#pragma unroll
        for (int it = 0; it < 8; it++) {
            int i = tid + it * 256;
            int e = i >> 4, q = i & 15;
            int n = n0 + e; if (n > N - 1) n = N - 1;
            uint32_t dst = sb + NA_OFF + e * 256 + ((q ^ (e & 7)) << 4);
            cp_async16(dst, x + (size_t)n * 128 + h * 64 + q * 4);
        }
        asm volatile("cp.async.commit_group;" ::: "memory");
        asm volatile("cp.async.wait_group 0;" ::: "memory");
        __syncthreads();

        const float* Abuf = (const float*)(smem + NA_OFF);
        const float* ar0 = Abuf + (wbase + g) * 64;
        const float* ar1 = Abuf + (wbase + 8 + g) * 64;
#pragma unroll
        for (int ks = 0; ks < 8; ks++) {
            int c0 = (((2 * ks)     ^ g) << 2) + t;
            int c1 = (((2 * ks + 1) ^ g) << 2) + t;
            uint32_t a0 = tf32r(ar0[c0]);
            uint32_t a1 = tf32r(ar1[c0]);
            uint32_t a2 = tf32r(ar0[c1]);
            uint32_t a3 = tf32r(ar1[c1]);
            const uint2* brow = B_s + (h * 8 + ks) * 512 + g * 4 + t;
#pragma unroll
            for (int nt = 0; nt < 16; nt++) {
                uint2 bv = brow[nt * 32];
                mma_tf32(acc[nt][0], acc[nt][1], acc[nt][2], acc[nt][3],
                         a0, a1, a2, a3, bv.x, bv.y);
            }
        }
        if (h == 0) __syncthreads();   // A buffer reused for half 1
    }

    // epilogue: add bias, store fp32 rows of g_xw
#pragma unroll
    for (int rs = 0; rs < 2; rs++) {
        int m = wbase + g + 8 * rs;
        int n = n0 + m;
        if (n >= N) continue;
        float* p = &g_xw[(size_t)n * 128];
#pragma unroll
        for (int q = 0; q < 8; q++) {
            int lc = q * 16 + 4 * t;
            float4 bv = *(const float4*)&bias_s[lc];
            float4 v = make_float4(acc[2 * q    ][rs * 2    ] + bv.x,
                                   acc[2 * q    ][rs * 2 + 1] + bv.y,
                                   acc[2 * q + 1][rs * 2    ] + bv.z,
                                   acc[2 * q + 1][rs * 2 + 1] + bv.w);
            *(float4*)&p[lc] = v;
        }
    }
}

// ---------------------------------------------------------------------------
// Kernel B: warp-PAIR edge pipeline, 256 threads (8 warps = 4 pairs), 2 CTA/SM.
// Pair j = {warps 2j, 2j+1} shares one 16-edge tile and one double-buffered A;
// warp h = wid&1 owns output cols [64h, 64h+64). acc 32 regs, gather 32 regs.
// Pair sync via named barriers bar.sync(1+j, 64). No block syncs in mainloop.
// smem: B @0 (32KB) | pair j: A bufs 2x4KB @ 32768 + j*8192   (64KB total)
// ---------------------------------------------------------------------------
#define AW_OFF  32768
#define EDGE_SMEM (AW_OFF + 4 * 8192)   // 65536

__global__ __launch_bounds__(256, 2)
void edge_mma_kernel(const int* __restrict__ eidx,   // [2][E] int32
                     const float* __restrict__ ea,   // [E][64]
                     const float* __restrict__ W,    // [192][128]
                     float* __restrict__ out,        // [N][128]
                     int E, int N, int ntiles) {
    extern __shared__ char smem[];
    const uint32_t sb = smem_u32(smem);
    uint2* B2 = (uint2*)smem;
    const uint4* B4 = (const uint4*)smem;

    const int tid  = threadIdx.x;
    const int wid  = tid >> 5, lane = tid & 31;
    const int g    = lane >> 2, t = lane & 3;
    const int tp   = g * 4 + t;
    const int j    = wid >> 1;        // pair id 0..3
    const int h    = wid & 1;         // column half
    const int barid = 1 + j;

    // build B fragments from W rows [0,64), paired uint4 layout
    for (int i = tid; i < 8192; i += 256) {
        int c = i & 3, n = (i >> 2) & 127, ks = i >> 9;
        int l = colperm(n);
        int k0 = ks * 8 + c;
        uint2 v = make_uint2(tf32r(W[(size_t)k0 * 128 + l]),
                             tf32r(W[(size_t)(k0 + 4) * 128 + l]));
        int nt = n >> 3, gg = n & 7;
        int i2 = ks * 512 + (nt >> 1) * 64 + (gg * 4 + c) * 2 + (nt & 1);
        B2[i2] = v;
    }
    __syncthreads();

    const uint32_t a_base = sb + AW_OFF + j * 8192;
    const float*   a_ptr0 = (const float*)(smem + AW_OFF + j * 8192);

    // cooperative pair issue: warp h loads edges [8h, 8h+8) of the tile
    auto issue = [&](int et2, int p2) {
        size_t ebase = (size_t)et2 * 16;
#pragma unroll
        for (int it = 0; it < 4; it++) {
            int i = h * 128 + lane + it * 32;   // 128 chunks per warp
            int e = i >> 4, q = i & 15;
            size_t se = ebase + e;
            if (se > (size_t)E - 1) se = (size_t)E - 1;
            cp_async16(a_base + p2 * 4096 + e * 256 + ((q ^ (e & 7)) << 4),
                       ea + se * 64 + q * 4);
        }
        asm volatile("cp.async.commit_group;" ::: "memory");
    };

    const int stride = gridDim.x * 4;
    int et = blockIdx.x * 4 + j;
    int p = 0;
    int s0 = -1, d0 = -1, s1 = -1, d1 = -1;
    if (et < ntiles) {
        issue(et, 0);
        size_t ebase = (size_t)et * 16;
        if (ebase + g < (size_t)E) {
            s0 = eidx[ebase + g];
            d0 = eidx[(size_t)E + ebase + g];
        }
        if (ebase + g + 8 < (size_t)E) {
            s1 = eidx[ebase + g + 8];
            d1 = eidx[(size_t)E + ebase + g + 8];
        }
    }

    for (; et < ntiles; et += stride) {
        // (a) gather prefetch into regs: this warp's column half only
        int ss0 = ((unsigned)s0 < (unsigned)N) ? s0 : 0;
        int ss1 = ((unsigned)s1 < (unsigned)N) ? s1 : 0;
        float4 gv0[4], gv1[4];
        {
            const float* gp0 = g_xw + (size_t)ss0 * 128 + h * 64 + 4 * t;
            const float* gp1 = g_xw + (size_t)ss1 * 128 + h * 64 + 4 * t;
#pragma unroll
            for (int q = 0; q < 4; q++) gv0[q] = ldg_v4(gp0 + q * 16);
#pragma unroll
            for (int q = 0; q < 4; q++) gv1[q] = ldg_v4(gp1 + q * 16);
        }

        // (b) bar A: partner finished reading buffer p^1 (prev iteration)
        asm volatile("bar.sync %0, 64;" :: "r"(barid) : "memory");

        int next = et + stride;
        int ns0 = -1, nd0 = -1, ns1 = -1, nd1 = -1;
        if (next < ntiles) {
            issue(next, p ^ 1);
            size_t nb = (size_t)next * 16;
            if (nb + g < (size_t)E) {
                ns0 = eidx[nb + g];
                nd0 = eidx[(size_t)E + nb + g];
            }
            if (nb + g + 8 < (size_t)E) {
                ns1 = eidx[nb + g + 8];
                nd1 = eidx[(size_t)E + nb + g + 8];
            }
            asm volatile("cp.async.wait_group 1;" ::: "memory");
        } else {
            asm volatile("cp.async.wait_group 0;" ::: "memory");
        }
        // (c) bar B: partner's writes to buffer p have landed too
        asm volatile("bar.sync %0, 64;" :: "r"(barid) : "memory");

        // (d) MMA from buffer p: 16 edges x 64 cols (this half)
        float acc[8][4];
#pragma unroll
        for (int nt = 0; nt < 8; nt++)
#pragma unroll
            for (int jj = 0; jj < 4; jj++) acc[nt][jj] = 0.0f;

        const float* Abuf = a_ptr0 + p * 1024;
        const float* ar0 = Abuf + g * 64;
        const float* ar1 = Abuf + (8 + g) * 64;
#pragma unroll
        for (int ks = 0; ks < 8; ks++) {
            int c0 = (((2 * ks)     ^ g) << 2) + t;
            int c1 = (((2 * ks + 1) ^ g) << 2) + t;
            uint32_t a0 = tf32r(ar0[c0]);
            uint32_t a1 = tf32r(ar1[c0]);
            uint32_t a2 = tf32r(ar0[c1]);
            uint32_t a3 = tf32r(ar1[c1]);
            const uint4* b4 = B4 + ks * 256 + h * 128 + tp;
#pragma unroll
            for (int pp = 0; pp < 4; pp++) {
                uint4 bw = b4[pp * 32];
                mma_tf32(acc[2 * pp    ][0], acc[2 * pp    ][1],
                         acc[2 * pp    ][2], acc[2 * pp    ][3],
                         a0, a1, a2, a3, bw.x, bw.y);
                mma_tf32(acc[2 * pp + 1][0], acc[2 * pp + 1][1],
                         acc[2 * pp + 1][2], acc[2 * pp + 1][3],
                         a0, a1, a2, a3, bw.z, bw.w);
            }
        }

        // (e) epilogue: ReLU(acc + gathered) -> vector atomic scatter (half cols)
        size_t ebase = (size_t)et * 16;
#pragma unroll
        for (int rs = 0; rs < 2; rs++) {
            int d = rs ? d1 : d0;
            int m = g + 8 * rs;
            if (ebase + m >= (size_t)E || (unsigned)d >= (unsigned)N) continue;
            float* op = &out[(size_t)d * 128 + h * 64];
            float4* gvp = rs ? gv1 : gv0;
#pragma unroll
            for (int q = 0; q < 4; q++) {
                int lc = q * 16 + 4 * t;
                float4 gvv = gvp[q];
                float v0 = fmaxf(acc[2 * q    ][rs * 2    ] + gvv.x, 0.f);
                float v1 = fmaxf(acc[2 * q    ][rs * 2 + 1] + gvv.y, 0.f);
                float v2 = fmaxf(acc[2 * q + 1][rs * 2    ] + gvv.z, 0.f);
                float v3 = fmaxf(acc[2 * q + 1][rs * 2 + 1] + gvv.w, 0.f);
                red_add_v4(op + lc, v0, v1, v2, v3);
            }
        }
        s0 = ns0; d0 = nd0; s1 = ns1; d1 = nd1;
        p ^= 1;
    }
}

extern "C" void kernel_launch(void* const* d_in, const int* in_sizes, int n_in,
                              void* d_out, int out_size) {
    const float* x    = (const float*)d_in[0];
    const int*   eidx = (const int*)d_in[1];   // int32 [2][E]
    const float* ea   = (const float*)d_in[2];
    const float* W    = (const float*)d_in[3];
    const float* b    = (const float*)d_in[4];
    float* out = (float*)d_out;

    const int N = in_sizes[0] / 128;   // 50000
    const int E = in_sizes[2] / 64;    // 800000
    const int ntilesN = (N + 127) / 128;
    const int ntilesE = (E + 15) / 16; // 16-edge tiles

    cudaFuncSetAttribute(node_fused_kernel,
                         cudaFuncAttributeMaxDynamicSharedMemorySize, NODE_SMEM);
    cudaFuncSetAttribute(edge_mma_kernel,
                         cudaFuncAttributeMaxDynamicSharedMemorySize, EDGE_SMEM);

    node_fused_kernel<<<NB_ZERO + ntilesN, 256, NODE_SMEM>>>(x, W, b, out, out_size, N, ntilesN);

    edge_mma_kernel<<<296, 256, EDGE_SMEM>>>(eidx, ea, W, out, E, N, ntilesE);
}